// round 3
// baseline (speedup 1.0000x reference)
#include <cuda_runtime.h>

// ---------------------------------------------------------------------------
// DifferentiableRenderer: Gaussian splat weighted-average render.
// out[b,c,y,x] = sum_n w_n*color_n / (sum_n w_n + 1e-8)
// w_n = opacity_n * exp(-0.5*((x-u_n)^2+(y-v_n)^2)/var_n)
//
// Strategy:
//   prep kernel:   per (b,n) compute u, v, a = -0.5*log2e/var, bop = log2(op)
//   render kernel: each thread = 4 pixels (one row) x 1 gaussian slice (of 8);
//                  accumulate in log2 domain with ex2.approx; reduce slices
//                  in shared memory; divide + store coalesced.
// ---------------------------------------------------------------------------

#define HH 128
#define WW 128
#define HWP (HH * WW)
#define FXC 150.0f
#define FYC 150.0f
#define CXC 64.0f
#define CYC 64.0f
#define EPSC 1e-8f

#define MAXBN 16384   // max B*N entries in scratch (B=2, N=4096 -> 8192 used)

__device__ float4 g_ga[MAXBN];  // u, v, a, bop
__device__ float4 g_gb[MAXBN];  // cr, cg, cb, 0

__device__ __forceinline__ float ex2f(float x) {
    float y;
    asm("ex2.approx.ftz.f32 %0, %1;" : "=f"(y) : "f"(x));
    return y;
}

// ---------------------------------------------------------------------------
// Prep: one thread per (b, n)
// ---------------------------------------------------------------------------
__global__ void prep_kernel(const float* __restrict__ pos,
                            const float* __restrict__ col,
                            const float* __restrict__ opac,
                            const float* __restrict__ scal,
                            const float* __restrict__ qv,
                            const float* __restrict__ tv,
                            int N, int B) {
    int i = blockIdx.x * blockDim.x + threadIdx.x;
    if (i >= N * B) return;
    int b = i / N;
    int n = i - b * N;

    float qw = qv[b * 4 + 0], qx = qv[b * 4 + 1];
    float qy = qv[b * 4 + 2], qz = qv[b * 4 + 3];
    float inv = 1.0f / sqrtf(qw * qw + qx * qx + qy * qy + qz * qz);
    qw *= inv; qx *= inv; qy *= inv; qz *= inv;

    float R00 = 1.0f - 2.0f * (qy * qy + qz * qz);
    float R01 = 2.0f * (qx * qy - qz * qw);
    float R02 = 2.0f * (qx * qz + qy * qw);
    float R10 = 2.0f * (qx * qy + qz * qw);
    float R11 = 1.0f - 2.0f * (qx * qx + qz * qz);
    float R12 = 2.0f * (qy * qz - qx * qw);
    float R20 = 2.0f * (qx * qz - qy * qw);
    float R21 = 2.0f * (qy * qz + qx * qw);
    float R22 = 1.0f - 2.0f * (qx * qx + qy * qy);

    float px = pos[n * 3 + 0], py = pos[n * 3 + 1], pz = pos[n * 3 + 2];
    float cx = R00 * px + R01 * py + R02 * pz + tv[b * 3 + 0];
    float cy = R10 * px + R11 * py + R12 * pz + tv[b * 3 + 1];
    float cz = R20 * px + R21 * py + R22 * pz + tv[b * 3 + 2];

    float invz = 1.0f / cz;
    float u = cx * invz * FXC + CXC;
    float v = cy * invz * FYC + CYC;

    float s = scal[n];
    // a = -0.5 * log2(e) / var   (log2-domain exponent coefficient)
    float a = -0.72134752044448170f / (s * s);
    float bop = log2f(opac[n]);   // fold opacity into the exponent

    g_ga[i] = make_float4(u, v, a, bop);
    g_gb[i] = make_float4(col[n * 3 + 0], col[n * 3 + 1], col[n * 3 + 2], 0.0f);
}

// ---------------------------------------------------------------------------
// Render: block = 128 threads = 16 pixel-quads x 8 gaussian slices.
// Each thread handles 4 consecutive pixels in one row.
// ---------------------------------------------------------------------------
#define QUADS  16
#define SLICES 8
#define RTHREADS (QUADS * SLICES)

__global__ void __launch_bounds__(RTHREADS)
render_kernel(float* __restrict__ out, int N, int B) {
    const int tid   = threadIdx.x;
    const int slice = tid >> 4;       // 0..7
    const int quad  = tid & 15;       // 0..15

    const int gq      = blockIdx.x * QUADS + quad;   // global quad id
    const int pixbase = gq * 4;
    const int b       = pixbase >> 14;               // / 16384
    const int rem     = pixbase & (HWP - 1);         // y*128 + x0
    const float pyf   = (float)(rem >> 7);
    const float px0   = (float)(rem & 127);

    // Gaussian slice range for this thread
    const int base = b * N;
    const int i0   = (slice * N) / SLICES;
    const int i1   = ((slice + 1) * N) / SLICES;

    float den0 = 0.f, den1 = 0.f, den2 = 0.f, den3 = 0.f;
    float ar0 = 0.f, ar1 = 0.f, ar2 = 0.f, ar3 = 0.f;
    float ag0 = 0.f, ag1 = 0.f, ag2 = 0.f, ag3 = 0.f;
    float ab0 = 0.f, ab1 = 0.f, ab2 = 0.f, ab3 = 0.f;

    #pragma unroll 2
    for (int i = i0; i < i1; i++) {
        const float4 ga = __ldg(&g_ga[base + i]);   // u, v, a, bop
        const float4 gb = __ldg(&g_gb[base + i]);   // cr, cg, cb, -

        const float dv = pyf - ga.y;
        const float c2 = fmaf(ga.z * dv, dv, ga.w); // a*dv^2 + log2(op)

        const float du0 = (px0 + 0.0f) - ga.x;
        const float du1 = (px0 + 1.0f) - ga.x;
        const float du2 = (px0 + 2.0f) - ga.x;
        const float du3 = (px0 + 3.0f) - ga.x;

        const float w0 = ex2f(fmaf(ga.z * du0, du0, c2));
        const float w1 = ex2f(fmaf(ga.z * du1, du1, c2));
        const float w2 = ex2f(fmaf(ga.z * du2, du2, c2));
        const float w3 = ex2f(fmaf(ga.z * du3, du3, c2));

        den0 += w0; den1 += w1; den2 += w2; den3 += w3;
        ar0 = fmaf(w0, gb.x, ar0); ar1 = fmaf(w1, gb.x, ar1);
        ar2 = fmaf(w2, gb.x, ar2); ar3 = fmaf(w3, gb.x, ar3);
        ag0 = fmaf(w0, gb.y, ag0); ag1 = fmaf(w1, gb.y, ag1);
        ag2 = fmaf(w2, gb.y, ag2); ag3 = fmaf(w3, gb.y, ag3);
        ab0 = fmaf(w0, gb.z, ab0); ab1 = fmaf(w1, gb.z, ab1);
        ab2 = fmaf(w2, gb.z, ab2); ab3 = fmaf(w3, gb.z, ab3);
    }

    // Cross-slice reduction in shared memory: red[slice][quad][p] = {den,r,g,b}
    __shared__ float4 red[SLICES * QUADS * 4];
    float4* myred = &red[(slice * QUADS + quad) * 4];
    myred[0] = make_float4(den0, ar0, ag0, ab0);
    myred[1] = make_float4(den1, ar1, ag1, ab1);
    myred[2] = make_float4(den2, ar2, ag2, ab2);
    myred[3] = make_float4(den3, ar3, ag3, ab3);
    __syncthreads();

    if (tid < QUADS * 4) {
        const int q = tid >> 2;
        const int p = tid & 3;
        float4 acc = red[(0 * QUADS + q) * 4 + p];
        #pragma unroll
        for (int s = 1; s < SLICES; s++) {
            const float4 t = red[(s * QUADS + q) * 4 + p];
            acc.x += t.x; acc.y += t.y; acc.z += t.z; acc.w += t.w;
        }
        const float invd = 1.0f / (acc.x + EPSC);

        const int gq2  = blockIdx.x * QUADS + q;
        const int pb   = gq2 * 4;
        const int bb   = pb >> 14;
        const int pix  = (pb & (HWP - 1)) + p;
        float* ob = out + (size_t)bb * 3 * HWP + pix;
        ob[0]        = acc.y * invd;   // R plane
        ob[HWP]      = acc.z * invd;   // G plane
        ob[2 * HWP]  = acc.w * invd;   // B plane
    }
}

// ---------------------------------------------------------------------------
extern "C" void kernel_launch(void* const* d_in, const int* in_sizes, int n_in,
                              void* d_out, int out_size) {
    const float* positions = (const float*)d_in[0];
    const float* colors    = (const float*)d_in[1];
    const float* opacities = (const float*)d_in[2];
    const float* scales    = (const float*)d_in[3];
    const float* qvec      = (const float*)d_in[4];
    const float* tvec      = (const float*)d_in[5];
    float* out = (float*)d_out;

    const int N = in_sizes[0] / 3;
    const int B = in_sizes[4] / 4;

    const int totalBN = N * B;
    prep_kernel<<<(totalBN + 255) / 256, 256>>>(positions, colors, opacities,
                                                scales, qvec, tvec, N, B);

    const int quads  = B * HWP / 4;          // 4 pixels per quad
    const int blocks = quads / QUADS;        // 16 quads per block
    render_kernel<<<blocks, RTHREADS>>>(out, N, B);
}

// round 5
// speedup vs baseline: 1.7034x; 1.7034x over previous
#include <cuda_runtime.h>

// ---------------------------------------------------------------------------
// DifferentiableRenderer: Gaussian splat weighted-average render.
// out[b,c,y,x] = sum_n w_n*color_n / (sum_n w_n + 1e-8)
// w_n = opacity_n * exp(-0.5*((x-u_n)^2+(y-v_n)^2)/var_n)
//
// R4 (= R3 re-bench after infra flake):
//   f32x2 packed math (halves fma-pipe instrs) + 2x occupancy (16 slices,
//   256-thread blocks) + prep-side operand broadcasting to kill in-loop MOVs.
//   unroll 4 -> 2 to bound register pressure.
// ---------------------------------------------------------------------------

#define HH 128
#define WW 128
#define HWP (HH * WW)
#define FXC 150.0f
#define FYC 150.0f
#define CXC 64.0f
#define CYC 64.0f
#define EPSC 1e-8f

#define MAXBN 16384   // max B*N entries in scratch (B=2, N=4096 -> 8192 used)

typedef unsigned long long ull;

// Packed per-gaussian operands (prepared once per launch):
__device__ ulonglong2 g_pa[MAXBN];  // { pack(-u,-u),  pack(a,a)   }
__device__ ulonglong2 g_pb[MAXBN];  // { pack(cr,cr),  pack(cg,cg) }
__device__ ulonglong2 g_pc[MAXBN];  // { pack(cb,cb),  pack(-v,bop) }

__device__ __forceinline__ float ex2f(float x) {
    float y;
    asm("ex2.approx.ftz.f32 %0, %1;" : "=f"(y) : "f"(x));
    return y;
}
__device__ __forceinline__ ull pk(float lo, float hi) {
    ull r; asm("mov.b64 %0, {%1, %2};" : "=l"(r) : "f"(lo), "f"(hi)); return r;
}
__device__ __forceinline__ float2 upk(ull v) {
    float2 r; asm("mov.b64 {%0, %1}, %2;" : "=f"(r.x), "=f"(r.y) : "l"(v)); return r;
}
__device__ __forceinline__ ull addx2(ull a, ull b) {
    ull r; asm("add.rn.f32x2 %0, %1, %2;" : "=l"(r) : "l"(a), "l"(b)); return r;
}
__device__ __forceinline__ ull mulx2(ull a, ull b) {
    ull r; asm("mul.rn.f32x2 %0, %1, %2;" : "=l"(r) : "l"(a), "l"(b)); return r;
}
__device__ __forceinline__ ull fmax2(ull a, ull b, ull c) {
    ull r; asm("fma.rn.f32x2 %0, %1, %2, %3;" : "=l"(r) : "l"(a), "l"(b), "l"(c));
    return r;
}

// ---------------------------------------------------------------------------
// Prep: one thread per (b, n)
// ---------------------------------------------------------------------------
__global__ void prep_kernel(const float* __restrict__ pos,
                            const float* __restrict__ col,
                            const float* __restrict__ opac,
                            const float* __restrict__ scal,
                            const float* __restrict__ qv,
                            const float* __restrict__ tv,
                            int N, int B) {
    int i = blockIdx.x * blockDim.x + threadIdx.x;
    if (i >= N * B) return;
    int b = i / N;
    int n = i - b * N;

    float qw = qv[b * 4 + 0], qx = qv[b * 4 + 1];
    float qy = qv[b * 4 + 2], qz = qv[b * 4 + 3];
    float inv = 1.0f / sqrtf(qw * qw + qx * qx + qy * qy + qz * qz);
    qw *= inv; qx *= inv; qy *= inv; qz *= inv;

    float R00 = 1.0f - 2.0f * (qy * qy + qz * qz);
    float R01 = 2.0f * (qx * qy - qz * qw);
    float R02 = 2.0f * (qx * qz + qy * qw);
    float R10 = 2.0f * (qx * qy + qz * qw);
    float R11 = 1.0f - 2.0f * (qx * qx + qz * qz);
    float R12 = 2.0f * (qy * qz - qx * qw);
    float R20 = 2.0f * (qx * qz - qy * qw);
    float R21 = 2.0f * (qy * qz + qx * qw);
    float R22 = 1.0f - 2.0f * (qx * qx + qy * qy);

    float px = pos[n * 3 + 0], py = pos[n * 3 + 1], pz = pos[n * 3 + 2];
    float cx = R00 * px + R01 * py + R02 * pz + tv[b * 3 + 0];
    float cy = R10 * px + R11 * py + R12 * pz + tv[b * 3 + 1];
    float cz = R20 * px + R21 * py + R22 * pz + tv[b * 3 + 2];

    float invz = 1.0f / cz;
    float u = cx * invz * FXC + CXC;
    float v = cy * invz * FYC + CYC;

    float s = scal[n];
    // a = -0.5 * log2(e) / var   (log2-domain exponent coefficient)
    float a = -0.72134752044448170f / (s * s);
    float bop = log2f(opac[n]);   // fold opacity into the exponent

    float cr = col[n * 3 + 0], cg = col[n * 3 + 1], cb = col[n * 3 + 2];

    ulonglong2 pa, pb, pc;
    pa.x = pk(-u, -u);  pa.y = pk(a, a);
    pb.x = pk(cr, cr);  pb.y = pk(cg, cg);
    pc.x = pk(cb, cb);  pc.y = pk(-v, bop);
    g_pa[i] = pa;
    g_pb[i] = pb;
    g_pc[i] = pc;
}

// ---------------------------------------------------------------------------
// Render: block = 256 threads = 16 pixel-quads x 16 gaussian slices.
// Each thread handles 4 consecutive pixels (two f32x2 pairs) of one row.
// ---------------------------------------------------------------------------
#define QUADS   16
#define SLICES  16
#define RTHREADS (QUADS * SLICES)

__global__ void __launch_bounds__(RTHREADS)
render_kernel(float* __restrict__ out, int N, int B) {
    __shared__ float4 red[SLICES * QUADS * 4];

    const int tid   = threadIdx.x;
    const int slice = tid >> 4;       // 0..15  (2 slices per warp -> broadcast loads)
    const int quad  = tid & 15;       // 0..15

    const int gq      = blockIdx.x * QUADS + quad;   // global quad id
    const int pixbase = gq * 4;
    const int b       = pixbase >> 14;               // / 16384
    const int rem     = pixbase & (HWP - 1);         // y*128 + x0
    const float pyf   = (float)(rem >> 7);
    const float px0   = (float)(rem & 127);

    const ull px01 = pk(px0 + 0.0f, px0 + 1.0f);
    const ull px23 = pk(px0 + 2.0f, px0 + 3.0f);

    // Gaussian slice range for this thread
    const int base = b * N;
    const int i0   = (slice * N) / SLICES;
    const int i1   = ((slice + 1) * N) / SLICES;

    ull den01 = 0, den23 = 0;
    ull ar01 = 0, ar23 = 0;
    ull ag01 = 0, ag23 = 0;
    ull ab01 = 0, ab23 = 0;

    #pragma unroll 2
    for (int i = i0; i < i1; i++) {
        const ulonglong2 pa = __ldg(&g_pa[base + i]);  // (-u,-u), (a,a)
        const ulonglong2 pb = __ldg(&g_pb[base + i]);  // (cr,cr), (cg,cg)
        const ulonglong2 pc = __ldg(&g_pc[base + i]);  // (cb,cb), (-v,bop)

        const float2 vb = upk(pc.y);                   // -v, bop
        const float2 aa = upk(pa.y);                   // a (low half)

        // scalar column term: c2 = a*dv^2 + log2(op)
        const float dv = pyf + vb.x;
        const float c2 = fmaf(aa.x * dv, dv, vb.y);
        const ull c22  = pk(c2, c2);

        // packed row terms: e = a*du^2 + c2 for pixel pairs
        const ull du01 = addx2(px01, pa.x);
        const ull du23 = addx2(px23, pa.x);
        const ull e01  = fmax2(mulx2(pa.y, du01), du01, c22);
        const ull e23  = fmax2(mulx2(pa.y, du23), du23, c22);

        const float2 f01 = upk(e01);
        const float2 f23 = upk(e23);
        const float w0 = ex2f(f01.x);
        const float w1 = ex2f(f01.y);
        const float w2 = ex2f(f23.x);
        const float w3 = ex2f(f23.y);

        const ull w01 = pk(w0, w1);
        const ull w23 = pk(w2, w3);

        den01 = addx2(den01, w01);         den23 = addx2(den23, w23);
        ar01  = fmax2(w01, pb.x, ar01);    ar23  = fmax2(w23, pb.x, ar23);
        ag01  = fmax2(w01, pb.y, ag01);    ag23  = fmax2(w23, pb.y, ag23);
        ab01  = fmax2(w01, pc.x, ab01);    ab23  = fmax2(w23, pc.x, ab23);
    }

    // Cross-slice reduction in shared memory: red[slice][quad][p] = {den,r,g,b}
    {
        const float2 d01 = upk(den01), d23 = upk(den23);
        const float2 r01 = upk(ar01),  r23 = upk(ar23);
        const float2 g01 = upk(ag01),  g23 = upk(ag23);
        const float2 b01 = upk(ab01),  b23 = upk(ab23);
        float4* myred = &red[(slice * QUADS + quad) * 4];
        myred[0] = make_float4(d01.x, r01.x, g01.x, b01.x);
        myred[1] = make_float4(d01.y, r01.y, g01.y, b01.y);
        myred[2] = make_float4(d23.x, r23.x, g23.x, b23.x);
        myred[3] = make_float4(d23.y, r23.y, g23.y, b23.y);
    }
    __syncthreads();

    if (tid < QUADS * 4) {
        const int q = tid >> 2;
        const int p = tid & 3;
        float4 acc = red[(0 * QUADS + q) * 4 + p];
        #pragma unroll
        for (int s = 1; s < SLICES; s++) {
            const float4 t = red[(s * QUADS + q) * 4 + p];
            acc.x += t.x; acc.y += t.y; acc.z += t.z; acc.w += t.w;
        }
        const float invd = 1.0f / (acc.x + EPSC);

        const int gq2  = blockIdx.x * QUADS + q;
        const int pb   = gq2 * 4;
        const int bb   = pb >> 14;
        const int pix  = (pb & (HWP - 1)) + p;
        float* ob = out + (size_t)bb * 3 * HWP + pix;
        ob[0]        = acc.y * invd;   // R plane
        ob[HWP]      = acc.z * invd;   // G plane
        ob[2 * HWP]  = acc.w * invd;   // B plane
    }
}

// ---------------------------------------------------------------------------
extern "C" void kernel_launch(void* const* d_in, const int* in_sizes, int n_in,
                              void* d_out, int out_size) {
    const float* positions = (const float*)d_in[0];
    const float* colors    = (const float*)d_in[1];
    const float* opacities = (const float*)d_in[2];
    const float* scales    = (const float*)d_in[3];
    const float* qvec      = (const float*)d_in[4];
    const float* tvec      = (const float*)d_in[5];
    float* out = (float*)d_out;

    const int N = in_sizes[0] / 3;
    const int B = in_sizes[4] / 4;

    const int totalBN = N * B;
    prep_kernel<<<(totalBN + 255) / 256, 256>>>(positions, colors, opacities,
                                                scales, qvec, tvec, N, B);

    const int quads  = B * HWP / 4;          // 4 pixels per quad
    const int blocks = quads / QUADS;        // 16 quads per block
    render_kernel<<<blocks, RTHREADS>>>(out, N, B);
}